// round 3
// baseline (speedup 1.0000x reference)
#include <cuda_runtime.h>
#include <math.h>

// ----------------------------------------------------------------------------
// GAT pipeline: 2x GATConv + global max pool + 3-layer MLP
// N=50000 nodes, E=800000 edges (+N self loops), G=256 graphs
// ----------------------------------------------------------------------------

#define NN 50000
#define EE 800000
#define ET_MAX (EE + NN)
#define GG 256

// ---- scratch (device globals; no allocations allowed) ----
__device__ float4   g_h1[NN * 16];      // [N,64] layer-1 features (pre-aggregation)
__device__ float    g_ssrc1[NN * 4];    // [N,4]
__device__ float    g_sdst1[NN * 4];    // [N,4]
__device__ unsigned g_max1[NN * 4];     // encoded float max
__device__ float    g_den1[NN * 4];
__device__ float4   g_w1[ET_MAX];       // per-edge: raw score -> exp weight -> coef [ET,4]
__device__ float4   g_acc1[NN * 16];    // [N,64] aggregated
__device__ float4   g_h1o[NN * 16];     // [N,64] after bias+ELU
__device__ float4   g_h2[NN * 64];      // [N,256]
__device__ float    g_ssrc2[NN];
__device__ float    g_sdst2[NN];
__device__ unsigned g_max2[NN];
__device__ float    g_den2[NN];
__device__ float    g_w2[ET_MAX];       // per-edge: raw score -> exp weight -> coef
__device__ float4   g_acc2[NN * 64];    // [N,256]
__device__ unsigned g_pool[GG * 256];
__device__ float    g_poolf[GG * 256];
__device__ float    g_z1[GG * 512];
__device__ float    g_z2[GG * 1024];

// ---- helpers ----
__device__ __forceinline__ unsigned fenc(float f) {
    unsigned u = __float_as_uint(f);
    return (u & 0x80000000u) ? ~u : (u | 0x80000000u);
}
__device__ __forceinline__ float fdec(unsigned e) {
    return (e & 0x80000000u) ? __uint_as_float(e & 0x7fffffffu)
                             : __uint_as_float(~e);
}
__device__ __forceinline__ float lrelu(float v) { return v > 0.f ? v : 0.2f * v; }
__device__ __forceinline__ float elu(float v)   { return v > 0.f ? v : expm1f(v); }

// ---- init: zero all accumulators / maxes / denominators ----
__global__ void k_init(int n) {
    int i = blockIdx.x * blockDim.x + threadIdx.x;
    int stride = gridDim.x * blockDim.x;
    float4 z4 = make_float4(0.f, 0.f, 0.f, 0.f);
    for (int j = i; j < n * 64; j += stride) g_acc2[j] = z4;
    for (int j = i; j < n * 16; j += stride) g_acc1[j] = z4;
    for (int j = i; j < n * 4; j += stride) { g_max1[j] = 0u; g_den1[j] = 0.f; }
    for (int j = i; j < n; j += stride)     { g_max2[j] = 0u; g_den2[j] = 0.f; }
    for (int j = i; j < GG * 256; j += stride) g_pool[j] = 0u;
}

// ---- layer1 GEMM [N,27]x[27,64] + attention scores ----
__global__ void k_gemm1(const float* __restrict__ x, const float* __restrict__ W1,
                        const float* __restrict__ a_src, const float* __restrict__ a_dst,
                        int n) {
    __shared__ float Wsh[27 * 64];
    __shared__ float xs[4][27];
    int t = threadIdx.x;  // 256 threads = 4 nodes x 64 cols
    for (int i = t; i < 27 * 64; i += 256) Wsh[i] = W1[i];
    int n0 = blockIdx.x * 4;
    for (int i = t; i < 4 * 27; i += 256) {
        int nl = i / 27, k = i % 27;
        int nn = n0 + nl;
        xs[nl][k] = (nn < n) ? x[nn * 27 + k] : 0.f;
    }
    __syncthreads();
    int nl = t >> 6, col = t & 63;
    int node = n0 + nl;
    float h = 0.f;
#pragma unroll
    for (int k = 0; k < 27; k++) h = fmaf(xs[nl][k], Wsh[k * 64 + col], h);
    int head = col >> 4, c = col & 15;
    float vs = h * a_src[head * 16 + c];
    float vd = h * a_dst[head * 16 + c];
#pragma unroll
    for (int o = 8; o >= 1; o >>= 1) {
        vs += __shfl_down_sync(0xffffffffu, vs, o, 16);
        vd += __shfl_down_sync(0xffffffffu, vd, o, 16);
    }
    if (node < n) {
        ((float*)g_h1)[node * 64 + col] = h;
        if (c == 0) {
            g_ssrc1[node * 4 + head] = vs;
            g_sdst1[node * 4 + head] = vd;
        }
    }
}

// ---- layer1 pass 1: compute score, stash it, segment max ----
__global__ void k_emax1(const int* __restrict__ ei, int e, int n) {
    int idx = blockIdx.x * blockDim.x + threadIdx.x;
    int et = e + n;
    if (idx >= et) return;
    int s, d;
    if (idx < e) { s = ei[idx]; d = ei[e + idx]; } else { s = d = idx - e; }
    float4 ss = *(const float4*)&g_ssrc1[s * 4];
    float4 sd = *(const float4*)&g_sdst1[d * 4];
    float a0 = lrelu(ss.x + sd.x);
    float a1 = lrelu(ss.y + sd.y);
    float a2 = lrelu(ss.z + sd.z);
    float a3 = lrelu(ss.w + sd.w);
    g_w1[idx] = make_float4(a0, a1, a2, a3);
    atomicMax(&g_max1[d * 4 + 0], fenc(a0));
    atomicMax(&g_max1[d * 4 + 1], fenc(a1));
    atomicMax(&g_max1[d * 4 + 2], fenc(a2));
    atomicMax(&g_max1[d * 4 + 3], fenc(a3));
}

// ---- layer1 pass 2: exp(score - max), segment sum ----
__global__ void k_esum1(const int* __restrict__ ei, int e, int n) {
    int idx = blockIdx.x * blockDim.x + threadIdx.x;
    int et = e + n;
    if (idx >= et) return;
    int d = (idx < e) ? ei[e + idx] : idx - e;
    float4 a = g_w1[idx];
    float w0 = __expf(a.x - fdec(g_max1[d * 4 + 0]));
    float w1 = __expf(a.y - fdec(g_max1[d * 4 + 1]));
    float w2 = __expf(a.z - fdec(g_max1[d * 4 + 2]));
    float w3 = __expf(a.w - fdec(g_max1[d * 4 + 3]));
    g_w1[idx] = make_float4(w0, w1, w2, w3);
    atomicAdd(&g_den1[d * 4 + 0], w0);
    atomicAdd(&g_den1[d * 4 + 1], w1);
    atomicAdd(&g_den1[d * 4 + 2], w2);
    atomicAdd(&g_den1[d * 4 + 3], w3);
}

// ---- layer1 coef: normalize per-edge weights in place ----
__global__ void k_coef1(const int* __restrict__ ei, int e, int n) {
    int idx = blockIdx.x * blockDim.x + threadIdx.x;
    int et = e + n;
    if (idx >= et) return;
    int d = (idx < e) ? ei[e + idx] : idx - e;
    float4 w = g_w1[idx];
    float4 den = *(const float4*)&g_den1[d * 4];
    w.x /= (den.x + 1e-16f);
    w.y /= (den.y + 1e-16f);
    w.z /= (den.z + 1e-16f);
    w.w /= (den.w + 1e-16f);
    g_w1[idx] = w;
}

// ---- layer1 aggregate: one thread per (edge, float4-chunk of 16) ----
__global__ void k_agg1(const int* __restrict__ ei, int e, int n) {
    int idx = blockIdx.x * blockDim.x + threadIdx.x;
    int et = e + n;
    if (idx >= et * 16) return;
    int ee = idx >> 4, q = idx & 15;
    int s, d;
    if (ee < e) { s = ei[ee]; d = ei[e + ee]; } else { s = d = ee - e; }
    int head = q >> 2;
    float coef = ((const float*)g_w1)[ee * 4 + head];
    float4 hv = g_h1[s * 16 + q];
    float4 v = make_float4(coef * hv.x, coef * hv.y, coef * hv.z, coef * hv.w);
    atomicAdd(&g_acc1[d * 16 + q], v);
}

// ---- layer1 finalize: +bias, ELU ----
__global__ void k_fin1(const float* __restrict__ b1, int n) {
    int idx = blockIdx.x * blockDim.x + threadIdx.x;
    if (idx >= n * 16) return;
    int q = idx & 15;
    float4 b = ((const float4*)b1)[q];
    float4 v = g_acc1[idx];
    v.x = elu(v.x + b.x); v.y = elu(v.y + b.y);
    v.z = elu(v.z + b.z); v.w = elu(v.w + b.w);
    g_h1o[idx] = v;
}

// ---- layer2 GEMM [N,64]x[64,256] ----
__global__ void k_gemm2(const float* __restrict__ W2, int n) {
    __shared__ float Wsh[32 * 256];
    __shared__ float xs[8][64];
    int t = threadIdx.x;  // 256 threads = 256 cols
    int n0 = blockIdx.x * 8;
    float acc[8] = {0.f, 0.f, 0.f, 0.f, 0.f, 0.f, 0.f, 0.f};
    for (int i = t; i < 8 * 64; i += 256) {
        int nl = i >> 6, k = i & 63;
        int nn = n0 + nl;
        xs[nl][k] = (nn < n) ? ((const float*)g_h1o)[nn * 64 + k] : 0.f;
    }
    for (int kc = 0; kc < 2; kc++) {
        __syncthreads();
        for (int i = t; i < 32 * 256; i += 256) Wsh[i] = W2[kc * 32 * 256 + i];
        __syncthreads();
#pragma unroll
        for (int k = 0; k < 32; k++) {
            float w = Wsh[k * 256 + t];
#pragma unroll
            for (int nl = 0; nl < 8; nl++)
                acc[nl] = fmaf(xs[nl][kc * 32 + k], w, acc[nl]);
        }
    }
    for (int nl = 0; nl < 8; nl++) {
        int nn = n0 + nl;
        if (nn < n) ((float*)g_h2)[nn * 256 + t] = acc[nl];
    }
}

// ---- layer2 attention scores: warp per node, dot(h2[n], a) over 256 ----
__global__ void k_s2(const float* __restrict__ a_src, const float* __restrict__ a_dst,
                     int n) {
    int warp = (blockIdx.x * blockDim.x + threadIdx.x) >> 5;
    int lane = threadIdx.x & 31;
    if (warp >= n) return;
    const float4* hp = &g_h2[warp * 64];
    float vs = 0.f, vd = 0.f;
#pragma unroll
    for (int i = 0; i < 2; i++) {
        float4 h = hp[lane + 32 * i];
        float4 as = ((const float4*)a_src)[lane + 32 * i];
        float4 ad = ((const float4*)a_dst)[lane + 32 * i];
        vs += h.x * as.x + h.y * as.y + h.z * as.z + h.w * as.w;
        vd += h.x * ad.x + h.y * ad.y + h.z * ad.z + h.w * ad.w;
    }
#pragma unroll
    for (int o = 16; o >= 1; o >>= 1) {
        vs += __shfl_down_sync(0xffffffffu, vs, o);
        vd += __shfl_down_sync(0xffffffffu, vd, o);
    }
    if (lane == 0) { g_ssrc2[warp] = vs; g_sdst2[warp] = vd; }
}

// ---- layer2 pass 1: compute score, stash it, segment max ----
__global__ void k_emax2(const int* __restrict__ ei, int e, int n) {
    int idx = blockIdx.x * blockDim.x + threadIdx.x;
    int et = e + n;
    if (idx >= et) return;
    int s, d;
    if (idx < e) { s = ei[idx]; d = ei[e + idx]; } else { s = d = idx - e; }
    float a = lrelu(g_ssrc2[s] + g_sdst2[d]);
    g_w2[idx] = a;
    atomicMax(&g_max2[d], fenc(a));
}

// ---- layer2 pass 2: exp(score - max), segment sum ----
__global__ void k_esum2(const int* __restrict__ ei, int e, int n) {
    int idx = blockIdx.x * blockDim.x + threadIdx.x;
    int et = e + n;
    if (idx >= et) return;
    int d = (idx < e) ? ei[e + idx] : idx - e;
    float w = __expf(g_w2[idx] - fdec(g_max2[d]));
    g_w2[idx] = w;
    atomicAdd(&g_den2[d], w);
}

// ---- layer2 coef: normalize per-edge weight in place ----
__global__ void k_coef2(const int* __restrict__ ei, int e, int n) {
    int idx = blockIdx.x * blockDim.x + threadIdx.x;
    int et = e + n;
    if (idx >= et) return;
    int d = (idx < e) ? ei[e + idx] : idx - e;
    g_w2[idx] = g_w2[idx] / (g_den2[d] + 1e-16f);
}

// ---- layer2 aggregate: one thread per (edge, float4-chunk of 64) ----
__global__ void k_agg2(const int* __restrict__ ei, int e, int n) {
    int idx = blockIdx.x * blockDim.x + threadIdx.x;
    int et = e + n;
    if (idx >= et * 64) return;
    int ee = idx >> 6, q = idx & 63;
    int s, d;
    if (ee < e) { s = ei[ee]; d = ei[e + ee]; } else { s = d = ee - e; }
    float coef = g_w2[ee];
    float4 hv = g_h2[s * 64 + q];
    float4 v = make_float4(coef * hv.x, coef * hv.y, coef * hv.z, coef * hv.w);
    atomicAdd(&g_acc2[d * 64 + q], v);
}

// ---- layer2 finalize: +bias, ELU, then per-graph max pool (atomicMax) ----
__global__ void k_fin2pool(const float* __restrict__ b2, const int* __restrict__ batch,
                           int n) {
    int idx = blockIdx.x * blockDim.x + threadIdx.x;
    if (idx >= n * 64) return;
    int q = idx & 63;
    int nn = idx >> 6;
    float4 b = ((const float4*)b2)[q];
    float4 v = g_acc2[idx];
    v.x = elu(v.x + b.x); v.y = elu(v.y + b.y);
    v.z = elu(v.z + b.z); v.w = elu(v.w + b.w);
    int g = batch[nn];
    unsigned* p = &g_pool[g * 256 + q * 4];
    atomicMax(&p[0], fenc(v.x));
    atomicMax(&p[1], fenc(v.y));
    atomicMax(&p[2], fenc(v.z));
    atomicMax(&p[3], fenc(v.w));
}

__global__ void k_poolf() {
    int i = blockIdx.x * blockDim.x + threadIdx.x;
    if (i < GG * 256) g_poolf[i] = fdec(g_pool[i]);
}

// ---- MLP layer 1: [G,256]x[256,512] + relu ----
__global__ void k_l1(const float* __restrict__ Wl1, const float* __restrict__ bl1) {
    __shared__ float ps[256];
    int g = blockIdx.x, t = threadIdx.x;  // 512 threads
    if (t < 256) ps[t] = g_poolf[g * 256 + t];
    __syncthreads();
    float acc = 0.f;
    for (int k = 0; k < 256; k++) acc = fmaf(ps[k], Wl1[k * 512 + t], acc);
    acc += bl1[t];
    g_z1[g * 512 + t] = acc > 0.f ? acc : 0.f;
}

// ---- MLP layer 2: [G,512]x[512,1024] + relu ----
__global__ void k_l2(const float* __restrict__ Wl2, const float* __restrict__ bl2) {
    __shared__ float ps[512];
    int g = blockIdx.x, t = threadIdx.x;  // 1024 threads
    if (t < 512) ps[t] = g_z1[g * 512 + t];
    __syncthreads();
    float acc = 0.f;
    for (int k = 0; k < 512; k++) acc = fmaf(ps[k], Wl2[k * 1024 + t], acc);
    acc += bl2[t];
    g_z2[g * 1024 + t] = acc > 0.f ? acc : 0.f;
}

// ---- MLP layer 3: [G,1024]x[1024,4] -> d_out ----
__global__ void k_l3(const float* __restrict__ Wl3, const float* __restrict__ bl3,
                     float* __restrict__ out) {
    int g = blockIdx.x;
    int wj = threadIdx.x >> 5;  // 4 warps, one per output col
    int lane = threadIdx.x & 31;
    float acc = 0.f;
    for (int k = lane; k < 1024; k += 32)
        acc = fmaf(g_z2[g * 1024 + k], Wl3[k * 4 + wj], acc);
#pragma unroll
    for (int o = 16; o >= 1; o >>= 1) acc += __shfl_down_sync(0xffffffffu, acc, o);
    if (lane == 0) out[g * 4 + wj] = acc + bl3[wj];
}

// ----------------------------------------------------------------------------
extern "C" void kernel_launch(void* const* d_in, const int* in_sizes, int n_in,
                              void* d_out, int out_size) {
    const float* x      = (const float*)d_in[0];
    const int*   ei     = (const int*)d_in[1];
    const int*   batch  = (const int*)d_in[2];
    const float* W1     = (const float*)d_in[3];
    const float* a_src1 = (const float*)d_in[4];
    const float* a_dst1 = (const float*)d_in[5];
    const float* b1     = (const float*)d_in[6];
    const float* W2     = (const float*)d_in[7];
    const float* a_src2 = (const float*)d_in[8];
    const float* a_dst2 = (const float*)d_in[9];
    const float* b2     = (const float*)d_in[10];
    const float* Wl1    = (const float*)d_in[11];
    const float* bl1    = (const float*)d_in[12];
    const float* Wl2    = (const float*)d_in[13];
    const float* bl2    = (const float*)d_in[14];
    const float* Wl3    = (const float*)d_in[15];
    const float* bl3    = (const float*)d_in[16];

    int n = in_sizes[0] / 27;
    int e = in_sizes[1] / 2;
    int et = e + n;

    k_init<<<2048, 256>>>(n);
    k_gemm1<<<(n + 3) / 4, 256>>>(x, W1, a_src1, a_dst1, n);
    k_emax1<<<(et + 255) / 256, 256>>>(ei, e, n);
    k_esum1<<<(et + 255) / 256, 256>>>(ei, e, n);
    k_coef1<<<(et + 255) / 256, 256>>>(ei, e, n);
    k_agg1<<<(et * 16 + 255) / 256, 256>>>(ei, e, n);
    k_fin1<<<(n * 16 + 255) / 256, 256>>>(b1, n);
    k_gemm2<<<(n + 7) / 8, 256>>>(W2, n);
    k_s2<<<(n + 3) / 4, 128>>>(a_src2, a_dst2, n);
    k_emax2<<<(et + 255) / 256, 256>>>(ei, e, n);
    k_esum2<<<(et + 255) / 256, 256>>>(ei, e, n);
    k_coef2<<<(et + 255) / 256, 256>>>(ei, e, n);
    k_agg2<<<(et * 64 + 255) / 256, 256>>>(ei, e, n);
    k_fin2pool<<<(n * 64 + 255) / 256, 256>>>(b2, batch, n);
    k_poolf<<<(GG * 256 + 255) / 256, 256>>>();
    k_l1<<<GG, 512>>>(Wl1, bl1);
    k_l2<<<GG, 1024>>>(Wl2, bl2);
    k_l3<<<GG, 128>>>(Wl3, bl3, (float*)d_out);
}

// round 4
// speedup vs baseline: 1.3889x; 1.3889x over previous
#include <cuda_runtime.h>
#include <math.h>

// ----------------------------------------------------------------------------
// GAT pipeline: 2x GATConv + global max pool + 3-layer MLP
// CSR (dst-sorted) gather formulation: zero atomics in softmax/aggregation.
// N=50000 nodes, E=800000 edges (+N self loops), G=256 graphs
// ----------------------------------------------------------------------------

#define NN 50000
#define EE 800000
#define ET_MAX (EE + NN)
#define GG 256

// ---- scratch (device globals; no allocations allowed) ----
__device__ float4   g_h1[NN * 16];      // [N,64] layer-1 features
__device__ float    g_ssrc1[NN * 4];
__device__ float    g_sdst1[NN * 4];
__device__ float4   g_h1o[NN * 16];     // [N,64] after agg+bias+ELU
__device__ float4   g_h2[NN * 64];      // [N,256]
__device__ float    g_ssrc2[NN];
__device__ float    g_sdst2[NN];
__device__ int      g_deg[NN];          // degree (incl self loop)
__device__ int      g_off[NN + 1];      // CSR offsets
__device__ int      g_cur[NN];          // scatter cursors
__device__ int      g_csrc[ET_MAX];     // CSR: source node per edge slot
__device__ float4   g_cw1[ET_MAX];      // CSR: layer1 score->weight->coef (4 heads)
__device__ float    g_cw2[ET_MAX];      // CSR: layer2 score->weight->coef
__device__ unsigned g_pool[GG * 256];
__device__ float    g_poolf[GG * 256];
__device__ float    g_z1[GG * 512];
__device__ float    g_z2[GG * 1024];

// ---- helpers ----
__device__ __forceinline__ unsigned fenc(float f) {
    unsigned u = __float_as_uint(f);
    return (u & 0x80000000u) ? ~u : (u | 0x80000000u);
}
__device__ __forceinline__ float fdec(unsigned e) {
    return (e & 0x80000000u) ? __uint_as_float(e & 0x7fffffffu)
                             : __uint_as_float(~e);
}
__device__ __forceinline__ float lrelu(float v) { return v > 0.f ? v : 0.2f * v; }
__device__ __forceinline__ float elu(float v)   { return v > 0.f ? v : expm1f(v); }

// ---- prep: deg=1 (self loop), zero pool ----
__global__ void k_prep(int n) {
    int i = blockIdx.x * blockDim.x + threadIdx.x;
    int stride = gridDim.x * blockDim.x;
    for (int j = i; j < n; j += stride) g_deg[j] = 1;
    for (int j = i; j < GG * 256; j += stride) g_pool[j] = 0u;
}

// ---- CSR build 1: histogram of destinations ----
__global__ void k_hist(const int* __restrict__ ei, int e) {
    int idx = blockIdx.x * blockDim.x + threadIdx.x;
    if (idx >= e) return;
    atomicAdd(&g_deg[ei[e + idx]], 1);
}

// ---- CSR build 2: exclusive scan (single block, 1024 threads) ----
__global__ void k_scan(int n) {
    __shared__ int ssum[1024];
    int t = threadIdx.x;
    const int per = (n + 1023) / 1024;
    int base = t * per;
    int local = 0;
    for (int i = 0; i < per; i++) {
        int idx = base + i;
        if (idx < n) local += g_deg[idx];
    }
    ssum[t] = local;
    __syncthreads();
    for (int o = 1; o < 1024; o <<= 1) {
        int v = (t >= o) ? ssum[t - o] : 0;
        __syncthreads();
        ssum[t] += v;
        __syncthreads();
    }
    int run = (t == 0) ? 0 : ssum[t - 1];
    for (int i = 0; i < per; i++) {
        int idx = base + i;
        if (idx < n) {
            g_off[idx] = run;
            g_cur[idx] = run;
            run += g_deg[idx];
        }
    }
    if (t == 1023) g_off[n] = run;
}

// ---- CSR build 3: scatter sources (edges + self loops) ----
__global__ void k_scatter(const int* __restrict__ ei, int e, int n) {
    int idx = blockIdx.x * blockDim.x + threadIdx.x;
    int et = e + n;
    if (idx >= et) return;
    int s, d;
    if (idx < e) { s = ei[idx]; d = ei[e + idx]; } else { s = d = idx - e; }
    int pos = atomicAdd(&g_cur[d], 1);
    g_csrc[pos] = s;
}

// ---- layer1 GEMM [N,27]x[27,64] + attention scores ----
__global__ void k_gemm1(const float* __restrict__ x, const float* __restrict__ W1,
                        const float* __restrict__ a_src, const float* __restrict__ a_dst,
                        int n) {
    __shared__ float Wsh[27 * 64];
    __shared__ float xs[4][27];
    int t = threadIdx.x;  // 256 threads = 4 nodes x 64 cols
    for (int i = t; i < 27 * 64; i += 256) Wsh[i] = W1[i];
    int n0 = blockIdx.x * 4;
    for (int i = t; i < 4 * 27; i += 256) {
        int nl = i / 27, k = i % 27;
        int nn = n0 + nl;
        xs[nl][k] = (nn < n) ? x[nn * 27 + k] : 0.f;
    }
    __syncthreads();
    int nl = t >> 6, col = t & 63;
    int node = n0 + nl;
    float h = 0.f;
#pragma unroll
    for (int k = 0; k < 27; k++) h = fmaf(xs[nl][k], Wsh[k * 64 + col], h);
    int head = col >> 4, c = col & 15;
    float vs = h * a_src[head * 16 + c];
    float vd = h * a_dst[head * 16 + c];
#pragma unroll
    for (int o = 8; o >= 1; o >>= 1) {
        vs += __shfl_down_sync(0xffffffffu, vs, o, 16);
        vd += __shfl_down_sync(0xffffffffu, vd, o, 16);
    }
    if (node < n) {
        ((float*)g_h1)[node * 64 + col] = h;
        if (c == 0) {
            g_ssrc1[node * 4 + head] = vs;
            g_sdst1[node * 4 + head] = vd;
        }
    }
}

// ---- layer1 softmax: one warp per dst node, full softmax over its segment ----
__global__ void k_soft1(int n) {
    int w = (blockIdx.x * blockDim.x + threadIdx.x) >> 5;
    int lane = threadIdx.x & 31;
    if (w >= n) return;
    int off = g_off[w], end = g_off[w + 1];
    float4 sd = *(const float4*)&g_sdst1[w * 4];
    float4 mx = make_float4(-1e30f, -1e30f, -1e30f, -1e30f);
    for (int p = off + lane; p < end; p += 32) {
        int s = g_csrc[p];
        float4 ss = *(const float4*)&g_ssrc1[s * 4];
        float4 a = make_float4(lrelu(ss.x + sd.x), lrelu(ss.y + sd.y),
                               lrelu(ss.z + sd.z), lrelu(ss.w + sd.w));
        g_cw1[p] = a;
        mx.x = fmaxf(mx.x, a.x); mx.y = fmaxf(mx.y, a.y);
        mx.z = fmaxf(mx.z, a.z); mx.w = fmaxf(mx.w, a.w);
    }
#pragma unroll
    for (int o = 16; o >= 1; o >>= 1) {
        mx.x = fmaxf(mx.x, __shfl_xor_sync(0xffffffffu, mx.x, o));
        mx.y = fmaxf(mx.y, __shfl_xor_sync(0xffffffffu, mx.y, o));
        mx.z = fmaxf(mx.z, __shfl_xor_sync(0xffffffffu, mx.z, o));
        mx.w = fmaxf(mx.w, __shfl_xor_sync(0xffffffffu, mx.w, o));
    }
    float4 sum = make_float4(0.f, 0.f, 0.f, 0.f);
    for (int p = off + lane; p < end; p += 32) {
        float4 a = g_cw1[p];
        float4 wv = make_float4(__expf(a.x - mx.x), __expf(a.y - mx.y),
                                __expf(a.z - mx.z), __expf(a.w - mx.w));
        g_cw1[p] = wv;
        sum.x += wv.x; sum.y += wv.y; sum.z += wv.z; sum.w += wv.w;
    }
#pragma unroll
    for (int o = 16; o >= 1; o >>= 1) {
        sum.x += __shfl_xor_sync(0xffffffffu, sum.x, o);
        sum.y += __shfl_xor_sync(0xffffffffu, sum.y, o);
        sum.z += __shfl_xor_sync(0xffffffffu, sum.z, o);
        sum.w += __shfl_xor_sync(0xffffffffu, sum.w, o);
    }
    float4 inv = make_float4(1.f / (sum.x + 1e-16f), 1.f / (sum.y + 1e-16f),
                             1.f / (sum.z + 1e-16f), 1.f / (sum.w + 1e-16f));
    for (int p = off + lane; p < end; p += 32) {
        float4 wv = g_cw1[p];
        wv.x *= inv.x; wv.y *= inv.y; wv.z *= inv.z; wv.w *= inv.w;
        g_cw1[p] = wv;
    }
}

// ---- layer1 gather-aggregate + bias + ELU (half-warp of 16 per node) ----
__global__ void k_gagg1(const float* __restrict__ b1, int n) {
    int gid = blockIdx.x * blockDim.x + threadIdx.x;
    int node = gid >> 4;
    if (node >= n) return;
    int q = gid & 15;               // float4 chunk 0..15, head = q>>2
    int head = q >> 2;
    int off = g_off[node], end = g_off[node + 1];
    float4 acc = make_float4(0.f, 0.f, 0.f, 0.f);
    for (int p = off; p < end; p++) {
        int s = g_csrc[p];                              // broadcast
        float c = ((const float*)g_cw1)[p * 4 + head];  // near-broadcast
        float4 h = g_h1[s * 16 + q];                    // 256B contiguous/16 lanes
        acc.x = fmaf(c, h.x, acc.x); acc.y = fmaf(c, h.y, acc.y);
        acc.z = fmaf(c, h.z, acc.z); acc.w = fmaf(c, h.w, acc.w);
    }
    float4 b = ((const float4*)b1)[q];
    acc.x = elu(acc.x + b.x); acc.y = elu(acc.y + b.y);
    acc.z = elu(acc.z + b.z); acc.w = elu(acc.w + b.w);
    g_h1o[node * 16 + q] = acc;
}

// ---- layer2 GEMM [N,64]x[64,256] ----
__global__ void k_gemm2(const float* __restrict__ W2, int n) {
    __shared__ float Wsh[32 * 256];
    __shared__ float xs[8][64];
    int t = threadIdx.x;  // 256 threads = 256 cols
    int n0 = blockIdx.x * 8;
    float acc[8] = {0.f, 0.f, 0.f, 0.f, 0.f, 0.f, 0.f, 0.f};
    for (int i = t; i < 8 * 64; i += 256) {
        int nl = i >> 6, k = i & 63;
        int nn = n0 + nl;
        xs[nl][k] = (nn < n) ? ((const float*)g_h1o)[nn * 64 + k] : 0.f;
    }
    for (int kc = 0; kc < 2; kc++) {
        __syncthreads();
        for (int i = t; i < 32 * 256; i += 256) Wsh[i] = W2[kc * 32 * 256 + i];
        __syncthreads();
#pragma unroll
        for (int k = 0; k < 32; k++) {
            float w = Wsh[k * 256 + t];
#pragma unroll
            for (int nl = 0; nl < 8; nl++)
                acc[nl] = fmaf(xs[nl][kc * 32 + k], w, acc[nl]);
        }
    }
    for (int nl = 0; nl < 8; nl++) {
        int nn = n0 + nl;
        if (nn < n) ((float*)g_h2)[nn * 256 + t] = acc[nl];
    }
}

// ---- layer2 attention scores: warp per node ----
__global__ void k_s2(const float* __restrict__ a_src, const float* __restrict__ a_dst,
                     int n) {
    int warp = (blockIdx.x * blockDim.x + threadIdx.x) >> 5;
    int lane = threadIdx.x & 31;
    if (warp >= n) return;
    const float4* hp = &g_h2[warp * 64];
    float vs = 0.f, vd = 0.f;
#pragma unroll
    for (int i = 0; i < 2; i++) {
        float4 h = hp[lane + 32 * i];
        float4 as = ((const float4*)a_src)[lane + 32 * i];
        float4 ad = ((const float4*)a_dst)[lane + 32 * i];
        vs += h.x * as.x + h.y * as.y + h.z * as.z + h.w * as.w;
        vd += h.x * ad.x + h.y * ad.y + h.z * ad.z + h.w * ad.w;
    }
#pragma unroll
    for (int o = 16; o >= 1; o >>= 1) {
        vs += __shfl_down_sync(0xffffffffu, vs, o);
        vd += __shfl_down_sync(0xffffffffu, vd, o);
    }
    if (lane == 0) { g_ssrc2[warp] = vs; g_sdst2[warp] = vd; }
}

// ---- layer2 softmax: one warp per dst node ----
__global__ void k_soft2(int n) {
    int w = (blockIdx.x * blockDim.x + threadIdx.x) >> 5;
    int lane = threadIdx.x & 31;
    if (w >= n) return;
    int off = g_off[w], end = g_off[w + 1];
    float sd = g_sdst2[w];
    float mx = -1e30f;
    for (int p = off + lane; p < end; p += 32) {
        float a = lrelu(g_ssrc2[g_csrc[p]] + sd);
        g_cw2[p] = a;
        mx = fmaxf(mx, a);
    }
#pragma unroll
    for (int o = 16; o >= 1; o >>= 1)
        mx = fmaxf(mx, __shfl_xor_sync(0xffffffffu, mx, o));
    float sum = 0.f;
    for (int p = off + lane; p < end; p += 32) {
        float wv = __expf(g_cw2[p] - mx);
        g_cw2[p] = wv;
        sum += wv;
    }
#pragma unroll
    for (int o = 16; o >= 1; o >>= 1)
        sum += __shfl_xor_sync(0xffffffffu, sum, o);
    float inv = 1.f / (sum + 1e-16f);
    for (int p = off + lane; p < end; p += 32)
        g_cw2[p] *= inv;
}

// ---- layer2 gather-aggregate + bias + ELU + graph max-pool (2 warps/node) ----
__global__ void k_gagg2(const float* __restrict__ b2, const int* __restrict__ batch,
                        int n) {
    int gw = (blockIdx.x * blockDim.x + threadIdx.x) >> 5;
    int lane = threadIdx.x & 31;
    if (gw >= n * 2) return;
    int node = gw >> 1, half = gw & 1;
    int q = half * 32 + lane;       // float4 chunk 0..63
    int off = g_off[node], end = g_off[node + 1];
    float4 acc = make_float4(0.f, 0.f, 0.f, 0.f);
    for (int p = off; p < end; p++) {
        int s = g_csrc[p];          // broadcast
        float c = g_cw2[p];         // broadcast
        float4 h = g_h2[s * 64 + q];  // 512B contiguous per warp
        acc.x = fmaf(c, h.x, acc.x); acc.y = fmaf(c, h.y, acc.y);
        acc.z = fmaf(c, h.z, acc.z); acc.w = fmaf(c, h.w, acc.w);
    }
    float4 b = ((const float4*)b2)[q];
    acc.x = elu(acc.x + b.x); acc.y = elu(acc.y + b.y);
    acc.z = elu(acc.z + b.z); acc.w = elu(acc.w + b.w);
    int g = batch[node];
    unsigned* p4 = &g_pool[g * 256 + q * 4];
    atomicMax(&p4[0], fenc(acc.x));
    atomicMax(&p4[1], fenc(acc.y));
    atomicMax(&p4[2], fenc(acc.z));
    atomicMax(&p4[3], fenc(acc.w));
}

__global__ void k_poolf() {
    int i = blockIdx.x * blockDim.x + threadIdx.x;
    if (i < GG * 256) g_poolf[i] = fdec(g_pool[i]);
}

// ---- MLP layer 1: [G,256]x[256,512] + relu ----
__global__ void k_l1(const float* __restrict__ Wl1, const float* __restrict__ bl1) {
    __shared__ float ps[256];
    int g = blockIdx.x, t = threadIdx.x;  // 512 threads
    if (t < 256) ps[t] = g_poolf[g * 256 + t];
    __syncthreads();
    float acc = 0.f;
    for (int k = 0; k < 256; k++) acc = fmaf(ps[k], Wl1[k * 512 + t], acc);
    acc += bl1[t];
    g_z1[g * 512 + t] = acc > 0.f ? acc : 0.f;
}

// ---- MLP layer 2: [G,512]x[512,1024] + relu ----
__global__ void k_l2(const float* __restrict__ Wl2, const float* __restrict__ bl2) {
    __shared__ float ps[512];
    int g = blockIdx.x, t = threadIdx.x;  // 1024 threads
    if (t < 512) ps[t] = g_z1[g * 512 + t];
    __syncthreads();
    float acc = 0.f;
    for (int k = 0; k < 512; k++) acc = fmaf(ps[k], Wl2[k * 1024 + t], acc);
    acc += bl2[t];
    g_z2[g * 1024 + t] = acc > 0.f ? acc : 0.f;
}

// ---- MLP layer 3: [G,1024]x[1024,4] -> d_out ----
__global__ void k_l3(const float* __restrict__ Wl3, const float* __restrict__ bl3,
                     float* __restrict__ out) {
    int g = blockIdx.x;
    int wj = threadIdx.x >> 5;  // 4 warps, one per output col
    int lane = threadIdx.x & 31;
    float acc = 0.f;
    for (int k = lane; k < 1024; k += 32)
        acc = fmaf(g_z2[g * 1024 + k], Wl3[k * 4 + wj], acc);
#pragma unroll
    for (int o = 16; o >= 1; o >>= 1) acc += __shfl_down_sync(0xffffffffu, acc, o);
    if (lane == 0) out[g * 4 + wj] = acc + bl3[wj];
}

// ----------------------------------------------------------------------------
extern "C" void kernel_launch(void* const* d_in, const int* in_sizes, int n_in,
                              void* d_out, int out_size) {
    const float* x      = (const float*)d_in[0];
    const int*   ei     = (const int*)d_in[1];
    const int*   batch  = (const int*)d_in[2];
    const float* W1     = (const float*)d_in[3];
    const float* a_src1 = (const float*)d_in[4];
    const float* a_dst1 = (const float*)d_in[5];
    const float* b1     = (const float*)d_in[6];
    const float* W2     = (const float*)d_in[7];
    const float* a_src2 = (const float*)d_in[8];
    const float* a_dst2 = (const float*)d_in[9];
    const float* b2     = (const float*)d_in[10];
    const float* Wl1    = (const float*)d_in[11];
    const float* bl1    = (const float*)d_in[12];
    const float* Wl2    = (const float*)d_in[13];
    const float* bl2    = (const float*)d_in[14];
    const float* Wl3    = (const float*)d_in[15];
    const float* bl3    = (const float*)d_in[16];

    int n = in_sizes[0] / 27;
    int e = in_sizes[1] / 2;
    int et = e + n;

    k_prep<<<256, 256>>>(n);
    k_hist<<<(e + 255) / 256, 256>>>(ei, e);
    k_gemm1<<<(n + 3) / 4, 256>>>(x, W1, a_src1, a_dst1, n);   // overlap-friendly order
    k_scan<<<1, 1024>>>(n);
    k_scatter<<<(et + 255) / 256, 256>>>(ei, e, n);
    k_soft1<<<(n * 32 + 255) / 256, 256>>>(n);
    k_gagg1<<<(n * 16 + 255) / 256, 256>>>(b1, n);
    k_gemm2<<<(n + 7) / 8, 256>>>(W2, n);
    k_s2<<<(n + 3) / 4, 128>>>(a_src2, a_dst2, n);
    k_soft2<<<(n * 32 + 255) / 256, 256>>>(n);
    k_gagg2<<<(n * 64 + 255) / 256, 256>>>(b2, batch, n);
    k_poolf<<<(GG * 256 + 255) / 256, 256>>>();
    k_l1<<<GG, 512>>>(Wl1, bl1);
    k_l2<<<GG, 1024>>>(Wl2, bl2);
    k_l3<<<GG, 128>>>(Wl3, bl3, (float*)d_out);
}

// round 8
// speedup vs baseline: 2.2798x; 1.6415x over previous
#include <cuda_runtime.h>
#include <math.h>

// ----------------------------------------------------------------------------
// GAT pipeline: 2x GATConv + global max pool + 3-layer MLP
// CSR gather; layer-2 uses aggregate-then-transform (64-dim aggregation,
// h2 never materialized; scores via projected attention vectors).
// N=50000 nodes, E=800000 edges (+N self loops), G=256 graphs
// ----------------------------------------------------------------------------

#define NN 50000
#define EE 800000
#define ET_MAX (EE + NN)
#define GG 256
#define SCAN_B 512
#define NB_MAX 256   // supports n <= 131072

// ---- scratch (device globals; no allocations allowed) ----
__device__ float4   g_h1[NN * 16];      // [N,64] layer-1 features
__device__ float    g_ssrc1[NN * 4];
__device__ float    g_sdst1[NN * 4];
__device__ float4   g_h1o[NN * 16];     // [N,64] after agg+bias+ELU
__device__ float4   g_agg64[NN * 16];   // [N,64] layer-2 aggregated (pre-GEMM)
__device__ float    g_ssrc2[NN];
__device__ float    g_sdst2[NN];
__device__ float    g_psrc[64];         // W2 @ a_src2
__device__ float    g_pdst[64];         // W2 @ a_dst2
__device__ int      g_deg[NN];          // degree (incl self loop)
__device__ int      g_bsum[NB_MAX];     // scan block partials
__device__ int      g_off[NN + 1];      // CSR offsets
__device__ int      g_cur[NN];          // scatter cursors
__device__ int      g_csrc[ET_MAX];     // CSR: source node per edge slot
__device__ float4   g_cw1[ET_MAX];      // CSR: layer1 score->weight->coef (4 heads)
__device__ float    g_cw2[ET_MAX];      // CSR: layer2 score->weight->coef
__device__ unsigned g_pool[GG * 256];
__device__ float    g_z1[GG * 512];
__device__ float    g_z2[GG * 1024];

// ---- helpers ----
__device__ __forceinline__ unsigned fenc(float f) {
    unsigned u = __float_as_uint(f);
    return (u & 0x80000000u) ? ~u : (u | 0x80000000u);
}
__device__ __forceinline__ float fdec(unsigned e) {
    return (e & 0x80000000u) ? __uint_as_float(e & 0x7fffffffu)
                             : __uint_as_float(~e);
}
__device__ __forceinline__ float lrelu(float v) { return v > 0.f ? v : 0.2f * v; }
__device__ __forceinline__ float elu(float v)   { return v > 0.f ? v : expm1f(v); }

// ---- prep: deg=1 (self loop), zero pool ----
__global__ void k_prep(int n) {
    int i = blockIdx.x * blockDim.x + threadIdx.x;
    int stride = gridDim.x * blockDim.x;
    for (int j = i; j < n; j += stride) g_deg[j] = 1;
    for (int j = i; j < GG * 256; j += stride) g_pool[j] = 0u;
}

// ---- project attention vectors through W2: p[j] = sum_c W2[j,c]*a[c] ----
__global__ void k_proj(const float* __restrict__ W2,
                       const float* __restrict__ a_src, const float* __restrict__ a_dst) {
    int w = (blockIdx.x * blockDim.x + threadIdx.x) >> 5;  // 64 warps, one per j
    int lane = threadIdx.x & 31;
    if (w >= 64) return;
    const float* row = W2 + w * 256;
    float vs = 0.f, vd = 0.f;
    for (int c = lane; c < 256; c += 32) {
        float wv = row[c];
        vs = fmaf(wv, a_src[c], vs);
        vd = fmaf(wv, a_dst[c], vd);
    }
#pragma unroll
    for (int o = 16; o >= 1; o >>= 1) {
        vs += __shfl_down_sync(0xffffffffu, vs, o);
        vd += __shfl_down_sync(0xffffffffu, vd, o);
    }
    if (lane == 0) { g_psrc[w] = vs; g_pdst[w] = vd; }
}

// ---- CSR build 1: histogram of destinations ----
__global__ void k_hist(const int* __restrict__ ei, int e) {
    int idx = blockIdx.x * blockDim.x + threadIdx.x;
    if (idx >= e) return;
    atomicAdd(&g_deg[ei[e + idx]], 1);
}

// ---- CSR scan A: per-block partial sums ----
__global__ void k_scanA(int n) {
    __shared__ int sh[SCAN_B];
    int t = threadIdx.x;
    int i = blockIdx.x * SCAN_B + t;
    sh[t] = (i < n) ? g_deg[i] : 0;
    __syncthreads();
#pragma unroll
    for (int o = SCAN_B / 2; o >= 1; o >>= 1) {
        if (t < o) sh[t] += sh[t + o];
        __syncthreads();
    }
    if (t == 0) g_bsum[blockIdx.x] = sh[0];
}

// ---- CSR scan B: exclusive scan of block partials (single tiny block) ----
__global__ void k_scanB(int nb) {
    __shared__ int sh[NB_MAX];
    int t = threadIdx.x;
    int v = (t < nb) ? g_bsum[t] : 0;
    sh[t] = v;
    __syncthreads();
#pragma unroll
    for (int o = 1; o < NB_MAX; o <<= 1) {
        int u = (t >= o) ? sh[t - o] : 0;
        __syncthreads();
        sh[t] += u;
        __syncthreads();
    }
    if (t < nb) g_bsum[t] = sh[t] - v;   // exclusive prefix
}

// ---- CSR scan C: per-block local scan + block offset -> g_off, g_cur ----
__global__ void k_scanC(int n) {
    __shared__ int sh[SCAN_B];
    int t = threadIdx.x;
    int i = blockIdx.x * SCAN_B + t;
    int v = (i < n) ? g_deg[i] : 0;
    sh[t] = v;
    __syncthreads();
#pragma unroll
    for (int o = 1; o < SCAN_B; o <<= 1) {
        int u = (t >= o) ? sh[t - o] : 0;
        __syncthreads();
        sh[t] += u;
        __syncthreads();
    }
    int excl = sh[t] - v + g_bsum[blockIdx.x];
    if (i < n) {
        g_off[i] = excl;
        g_cur[i] = excl;
        if (i == n - 1) g_off[n] = excl + v;
    }
}

// ---- CSR build: scatter sources (edges + self loops) ----
__global__ void k_scatter(const int* __restrict__ ei, int e, int n) {
    int idx = blockIdx.x * blockDim.x + threadIdx.x;
    int et = e + n;
    if (idx >= et) return;
    int s, d;
    if (idx < e) { s = ei[idx]; d = ei[e + idx]; } else { s = d = idx - e; }
    int pos = atomicAdd(&g_cur[d], 1);
    g_csrc[pos] = s;
}

// ---- layer1 GEMM [N,27]x[27,64] + attention scores ----
__global__ void k_gemm1(const float* __restrict__ x, const float* __restrict__ W1,
                        const float* __restrict__ a_src, const float* __restrict__ a_dst,
                        int n) {
    __shared__ float Wsh[27 * 64];
    __shared__ float xs[4][27];
    int t = threadIdx.x;  // 256 threads = 4 nodes x 64 cols
    for (int i = t; i < 27 * 64; i += 256) Wsh[i] = W1[i];
    int n0 = blockIdx.x * 4;
    for (int i = t; i < 4 * 27; i += 256) {
        int nl = i / 27, k = i % 27;
        int nn = n0 + nl;
        xs[nl][k] = (nn < n) ? x[nn * 27 + k] : 0.f;
    }
    __syncthreads();
    int nl = t >> 6, col = t & 63;
    int node = n0 + nl;
    float h = 0.f;
#pragma unroll
    for (int k = 0; k < 27; k++) h = fmaf(xs[nl][k], Wsh[k * 64 + col], h);
    int head = col >> 4, c = col & 15;
    float vs = h * a_src[head * 16 + c];
    float vd = h * a_dst[head * 16 + c];
#pragma unroll
    for (int o = 8; o >= 1; o >>= 1) {
        vs += __shfl_down_sync(0xffffffffu, vs, o, 16);
        vd += __shfl_down_sync(0xffffffffu, vd, o, 16);
    }
    if (node < n) {
        ((float*)g_h1)[node * 64 + col] = h;
        if (c == 0) {
            g_ssrc1[node * 4 + head] = vs;
            g_sdst1[node * 4 + head] = vd;
        }
    }
}

// ---- layer1 softmax: one warp per dst node ----
__global__ void k_soft1(int n) {
    int w = (blockIdx.x * blockDim.x + threadIdx.x) >> 5;
    int lane = threadIdx.x & 31;
    if (w >= n) return;
    int off = g_off[w], end = g_off[w + 1];
    float4 sd = *(const float4*)&g_sdst1[w * 4];
    float4 mx = make_float4(-1e30f, -1e30f, -1e30f, -1e30f);
    for (int p = off + lane; p < end; p += 32) {
        int s = g_csrc[p];
        float4 ss = *(const float4*)&g_ssrc1[s * 4];
        float4 a = make_float4(lrelu(ss.x + sd.x), lrelu(ss.y + sd.y),
                               lrelu(ss.z + sd.z), lrelu(ss.w + sd.w));
        g_cw1[p] = a;
        mx.x = fmaxf(mx.x, a.x); mx.y = fmaxf(mx.y, a.y);
        mx.z = fmaxf(mx.z, a.z); mx.w = fmaxf(mx.w, a.w);
    }
#pragma unroll
    for (int o = 16; o >= 1; o >>= 1) {
        mx.x = fmaxf(mx.x, __shfl_xor_sync(0xffffffffu, mx.x, o));
        mx.y = fmaxf(mx.y, __shfl_xor_sync(0xffffffffu, mx.y, o));
        mx.z = fmaxf(mx.z, __shfl_xor_sync(0xffffffffu, mx.z, o));
        mx.w = fmaxf(mx.w, __shfl_xor_sync(0xffffffffu, mx.w, o));
    }
    float4 sum = make_float4(0.f, 0.f, 0.f, 0.f);
    for (int p = off + lane; p < end; p += 32) {
        float4 a = g_cw1[p];
        float4 wv = make_float4(__expf(a.x - mx.x), __expf(a.y - mx.y),
                                __expf(a.z - mx.z), __expf(a.w - mx.w));
        g_cw1[p] = wv;
        sum.x += wv.x; sum.y += wv.y; sum.z += wv.z; sum.w += wv.w;
    }
#pragma unroll
    for (int o = 16; o >= 1; o >>= 1) {
        sum.x += __shfl_xor_sync(0xffffffffu, sum.x, o);
        sum.y += __shfl_xor_sync(0xffffffffu, sum.y, o);
        sum.z += __shfl_xor_sync(0xffffffffu, sum.z, o);
        sum.w += __shfl_xor_sync(0xffffffffu, sum.w, o);
    }
    float4 inv = make_float4(1.f / (sum.x + 1e-16f), 1.f / (sum.y + 1e-16f),
                             1.f / (sum.z + 1e-16f), 1.f / (sum.w + 1e-16f));
    for (int p = off + lane; p < end; p += 32) {
        float4 wv = g_cw1[p];
        wv.x *= inv.x; wv.y *= inv.y; wv.z *= inv.z; wv.w *= inv.w;
        g_cw1[p] = wv;
    }
}

// ---- layer1 gather-aggregate + bias + ELU + fused layer2 scores ----
// 16 threads per node (half-warp groups).
__global__ void k_gagg1(const float* __restrict__ b1, int n) {
    int gid = blockIdx.x * blockDim.x + threadIdx.x;
    int node = gid >> 4;
    if (node >= n) return;
    int q = gid & 15;               // float4 chunk 0..15, head = q>>2
    int head = q >> 2;
    int off = g_off[node], end = g_off[node + 1];
    float4 acc = make_float4(0.f, 0.f, 0.f, 0.f);
    for (int p = off; p < end; p++) {
        int s = g_csrc[p];
        float c = ((const float*)g_cw1)[p * 4 + head];
        float4 h = g_h1[s * 16 + q];
        acc.x = fmaf(c, h.x, acc.x); acc.y = fmaf(c, h.y, acc.y);
        acc.z = fmaf(c, h.z, acc.z); acc.w = fmaf(c, h.w, acc.w);
    }
    float4 b = ((const float4*)b1)[q];
    acc.x = elu(acc.x + b.x); acc.y = elu(acc.y + b.y);
    acc.z = elu(acc.z + b.z); acc.w = elu(acc.w + b.w);
    g_h1o[node * 16 + q] = acc;
    // fused layer2 attention scores: s = h1o . (W2 @ a)
    float4 ps = ((const float4*)g_psrc)[q];
    float4 pd = ((const float4*)g_pdst)[q];
    float vs = acc.x * ps.x + acc.y * ps.y + acc.z * ps.z + acc.w * ps.w;
    float vd = acc.x * pd.x + acc.y * pd.y + acc.z * pd.z + acc.w * pd.w;
#pragma unroll
    for (int o = 8; o >= 1; o >>= 1) {
        vs += __shfl_down_sync(0xffffffffu, vs, o, 16);
        vd += __shfl_down_sync(0xffffffffu, vd, o, 16);
    }
    if (q == 0) { g_ssrc2[node] = vs; g_sdst2[node] = vd; }
}

// ---- layer2 softmax: one warp per dst node ----
__global__ void k_soft2(int n) {
    int w = (blockIdx.x * blockDim.x + threadIdx.x) >> 5;
    int lane = threadIdx.x & 31;
    if (w >= n) return;
    int off = g_off[w], end = g_off[w + 1];
    float sd = g_sdst2[w];
    float mx = -1e30f;
    for (int p = off + lane; p < end; p += 32) {
        float a = lrelu(g_ssrc2[g_csrc[p]] + sd);
        g_cw2[p] = a;
        mx = fmaxf(mx, a);
    }
#pragma unroll
    for (int o = 16; o >= 1; o >>= 1)
        mx = fmaxf(mx, __shfl_xor_sync(0xffffffffu, mx, o));
    float sum = 0.f;
    for (int p = off + lane; p < end; p += 32) {
        float wv = __expf(g_cw2[p] - mx);
        g_cw2[p] = wv;
        sum += wv;
    }
#pragma unroll
    for (int o = 16; o >= 1; o >>= 1)
        sum += __shfl_xor_sync(0xffffffffu, sum, o);
    float inv = 1.f / (sum + 1e-16f);
    for (int p = off + lane; p < end; p += 32)
        g_cw2[p] *= inv;
}

// ---- layer2 aggregate in 64-dim: agg64[d] = sum_e coef_e * h1o[src] ----
// 16 threads per node.
__global__ void k_gagg2(int n) {
    int gid = blockIdx.x * blockDim.x + threadIdx.x;
    int node = gid >> 4;
    if (node >= n) return;
    int q = gid & 15;
    int off = g_off[node], end = g_off[node + 1];
    float4 acc = make_float4(0.f, 0.f, 0.f, 0.f);
    for (int p = off; p < end; p++) {
        int s = g_csrc[p];
        float c = g_cw2[p];
        float4 h = g_h1o[s * 16 + q];
        acc.x = fmaf(c, h.x, acc.x); acc.y = fmaf(c, h.y, acc.y);
        acc.z = fmaf(c, h.z, acc.z); acc.w = fmaf(c, h.w, acc.w);
    }
    g_agg64[node * 16 + q] = acc;
}

// ---- layer2 post-GEMM: [N,64]x[64,256] + bias + ELU + graph max-pool ----
__global__ void k_gemm2p(const float* __restrict__ W2, const float* __restrict__ b2,
                         const int* __restrict__ batch, int n) {
    __shared__ float Wsh[32 * 256];
    __shared__ float xs[8][64];
    int t = threadIdx.x;  // 256 threads = 256 cols
    int n0 = blockIdx.x * 8;
    float acc[8] = {0.f, 0.f, 0.f, 0.f, 0.f, 0.f, 0.f, 0.f};
    for (int i = t; i < 8 * 64; i += 256) {
        int nl = i >> 6, k = i & 63;
        int nn = n0 + nl;
        xs[nl][k] = (nn < n) ? ((const float*)g_agg64)[nn * 64 + k] : 0.f;
    }
    for (int kc = 0; kc < 2; kc++) {
        __syncthreads();
        for (int i = t; i < 32 * 256; i += 256) Wsh[i] = W2[kc * 32 * 256 + i];
        __syncthreads();
#pragma unroll
        for (int k = 0; k < 32; k++) {
            float w = Wsh[k * 256 + t];
#pragma unroll
            for (int nl = 0; nl < 8; nl++)
                acc[nl] = fmaf(xs[nl][kc * 32 + k], w, acc[nl]);
        }
    }
    float bb = b2[t];
    for (int nl = 0; nl < 8; nl++) {
        int nn = n0 + nl;
        if (nn < n) {
            float v = elu(acc[nl] + bb);
            atomicMax(&g_pool[batch[nn] * 256 + t], fenc(v));
        }
    }
}

// ---- MLP layer 1: [G,256]x[256,512] + relu (pool decode fused) ----
__global__ void k_l1(const float* __restrict__ Wl1, const float* __restrict__ bl1) {
    __shared__ float ps[256];
    int g = blockIdx.x, t = threadIdx.x;  // 512 threads
    if (t < 256) ps[t] = fdec(g_pool[g * 256 + t]);
    __syncthreads();
    float acc = 0.f;
    for (int k = 0; k < 256; k++) acc = fmaf(ps[k], Wl1[k * 512 + t], acc);
    acc += bl1[t];
    g_z1[g * 512 + t] = acc > 0.f ? acc : 0.f;
}

// ---- MLP layer 2: [G,512]x[512,1024] + relu ----
__global__ void k_l2(const float* __restrict__ Wl2, const float* __restrict__ bl2) {
    __shared__ float ps[512];
    int g = blockIdx.x, t = threadIdx.x;  // 1024 threads
    if (t < 512) ps[t] = g_z1[g * 512 + t];
    __syncthreads();
    float acc = 0.f;
    for (int k = 0; k < 512; k++) acc = fmaf(ps[k], Wl2[k * 1024 + t], acc);
    acc += bl2[t];
    g_z2[g * 1024 + t] = acc > 0.f ? acc : 0.f;
}

// ---- MLP layer 3: [G,1024]x[1024,4] -> d_out ----
__global__ void k_l3(const float* __restrict__ Wl3, const float* __restrict__ bl3,
                     float* __restrict__ out) {
    int g = blockIdx.x;
    int wj = threadIdx.x >> 5;  // 4 warps, one per output col
    int lane = threadIdx.x & 31;
    float acc = 0.f;
    for (int k = lane; k < 1024; k += 32)
        acc = fmaf(g_z2[g * 1024 + k], Wl3[k * 4 + wj], acc);
#pragma unroll
    for (int o = 16; o >= 1; o >>= 1) acc += __shfl_down_sync(0xffffffffu, acc, o);
    if (lane == 0) out[g * 4 + wj] = acc + bl3[wj];
}

// ----------------------------------------------------------------------------
extern "C" void kernel_launch(void* const* d_in, const int* in_sizes, int n_in,
                              void* d_out, int out_size) {
    const float* x      = (const float*)d_in[0];
    const int*   ei     = (const int*)d_in[1];
    const int*   batch  = (const int*)d_in[2];
    const float* W1     = (const float*)d_in[3];
    const float* a_src1 = (const float*)d_in[4];
    const float* a_dst1 = (const float*)d_in[5];
    const float* b1     = (const float*)d_in[6];
    const float* W2     = (const float*)d_in[7];
    const float* a_src2 = (const float*)d_in[8];
    const float* a_dst2 = (const float*)d_in[9];
    const float* b2     = (const float*)d_in[10];
    const float* Wl1    = (const float*)d_in[11];
    const float* bl1    = (const float*)d_in[12];
    const float* Wl2    = (const float*)d_in[13];
    const float* bl2    = (const float*)d_in[14];
    const float* Wl3    = (const float*)d_in[15];
    const float* bl3    = (const float*)d_in[16];

    int n = in_sizes[0] / 27;
    int e = in_sizes[1] / 2;
    int et = e + n;
    int nb = (n + SCAN_B - 1) / SCAN_B;

    k_prep<<<256, 256>>>(n);
    k_hist<<<(e + 255) / 256, 256>>>(ei, e);
    k_proj<<<4, 512>>>(W2, a_src2, a_dst2);
    k_gemm1<<<(n + 3) / 4, 256>>>(x, W1, a_src1, a_dst1, n);  // independent; overlaps
    k_scanA<<<nb, SCAN_B>>>(n);
    k_scanB<<<1, NB_MAX>>>(nb);
    k_scanC<<<nb, SCAN_B>>>(n);
    k_scatter<<<(et + 255) / 256, 256>>>(ei, e, n);
    k_soft1<<<(n * 32 + 255) / 256, 256>>>(n);
    k_gagg1<<<(n * 16 + 255) / 256, 256>>>(b1, n);
    k_soft2<<<(n * 32 + 255) / 256, 256>>>(n);
    k_gagg2<<<(n * 16 + 255) / 256, 256>>>(n);
    k_gemm2p<<<(n + 7) / 8, 256>>>(W2, b2, batch, n);
    k_l1<<<GG, 512>>>(Wl1, bl1);
    k_l2<<<GG, 1024>>>(Wl2, bl2);
    k_l3<<<GG, 128>>>(Wl3, bl3, (float*)d_out);
}

// round 9
// speedup vs baseline: 2.4294x; 1.0656x over previous
#include <cuda_runtime.h>
#include <math.h>

// ----------------------------------------------------------------------------
// GAT pipeline: 2x GATConv + global max pool + 3-layer MLP
// CSR gather; layer-2 aggregate-then-transform; register-cached W1 GEMM;
// fused MLP head. N=50000, E=800000 (+N self loops), G=256 graphs
// ----------------------------------------------------------------------------

#define NN 50000
#define EE 800000
#define ET_MAX (EE + NN)
#define GG 256
#define SCAN_B 512
#define NB_MAX 256   // supports n <= 131072

// ---- scratch (device globals; no allocations allowed) ----
__device__ float4   g_h1[NN * 16];      // [N,64] layer-1 features
__device__ float    g_ssrc1[NN * 4];
__device__ float    g_sdst1[NN * 4];
__device__ float4   g_h1o[NN * 16];     // [N,64] after agg+bias+ELU
__device__ float4   g_agg64[NN * 16];   // [N,64] layer-2 aggregated (pre-GEMM)
__device__ float    g_ssrc2[NN];
__device__ float    g_sdst2[NN];
__device__ float    g_psrc[64];         // W2 @ a_src2
__device__ float    g_pdst[64];         // W2 @ a_dst2
__device__ int      g_deg[NN];          // degree (incl self loop)
__device__ int      g_bsum[NB_MAX];     // scan block partials
__device__ int      g_off[NN + 1];      // CSR offsets
__device__ int      g_cur[NN];          // scatter cursors
__device__ int      g_csrc[ET_MAX];     // CSR: source node per edge slot
__device__ float4   g_cw1[ET_MAX];      // CSR: layer1 score->weight->coef (4 heads)
__device__ float    g_cw2[ET_MAX];      // CSR: layer2 score->weight->coef
__device__ unsigned g_pool[GG * 256];

// ---- helpers ----
__device__ __forceinline__ unsigned fenc(float f) {
    unsigned u = __float_as_uint(f);
    return (u & 0x80000000u) ? ~u : (u | 0x80000000u);
}
__device__ __forceinline__ float fdec(unsigned e) {
    return (e & 0x80000000u) ? __uint_as_float(e & 0x7fffffffu)
                             : __uint_as_float(~e);
}
__device__ __forceinline__ float lrelu(float v) { return v > 0.f ? v : 0.2f * v; }
__device__ __forceinline__ float elu(float v)   { return v > 0.f ? v : expm1f(v); }

// ---- prep: deg=1 (self loop), zero pool ----
__global__ void k_prep(int n) {
    int i = blockIdx.x * blockDim.x + threadIdx.x;
    int stride = gridDim.x * blockDim.x;
    for (int j = i; j < n; j += stride) g_deg[j] = 1;
    for (int j = i; j < GG * 256; j += stride) g_pool[j] = 0u;
}

// ---- project attention vectors through W2: p[j] = sum_c W2[j,c]*a[c] ----
__global__ void k_proj(const float* __restrict__ W2,
                       const float* __restrict__ a_src, const float* __restrict__ a_dst) {
    int w = (blockIdx.x * blockDim.x + threadIdx.x) >> 5;  // 64 warps, one per j
    int lane = threadIdx.x & 31;
    if (w >= 64) return;
    const float* row = W2 + w * 256;
    float vs = 0.f, vd = 0.f;
    for (int c = lane; c < 256; c += 32) {
        float wv = row[c];
        vs = fmaf(wv, a_src[c], vs);
        vd = fmaf(wv, a_dst[c], vd);
    }
#pragma unroll
    for (int o = 16; o >= 1; o >>= 1) {
        vs += __shfl_down_sync(0xffffffffu, vs, o);
        vd += __shfl_down_sync(0xffffffffu, vd, o);
    }
    if (lane == 0) { g_psrc[w] = vs; g_pdst[w] = vd; }
}

// ---- CSR build 1: histogram of destinations ----
__global__ void k_hist(const int* __restrict__ ei, int e) {
    int idx = blockIdx.x * blockDim.x + threadIdx.x;
    if (idx >= e) return;
    atomicAdd(&g_deg[ei[e + idx]], 1);
}

// ---- CSR scan A: per-block partial sums ----
__global__ void k_scanA(int n) {
    __shared__ int sh[SCAN_B];
    int t = threadIdx.x;
    int i = blockIdx.x * SCAN_B + t;
    sh[t] = (i < n) ? g_deg[i] : 0;
    __syncthreads();
#pragma unroll
    for (int o = SCAN_B / 2; o >= 1; o >>= 1) {
        if (t < o) sh[t] += sh[t + o];
        __syncthreads();
    }
    if (t == 0) g_bsum[blockIdx.x] = sh[0];
}

// ---- CSR scan B: exclusive scan of block partials ----
__global__ void k_scanB(int nb) {
    __shared__ int sh[NB_MAX];
    int t = threadIdx.x;
    int v = (t < nb) ? g_bsum[t] : 0;
    sh[t] = v;
    __syncthreads();
#pragma unroll
    for (int o = 1; o < NB_MAX; o <<= 1) {
        int u = (t >= o) ? sh[t - o] : 0;
        __syncthreads();
        sh[t] += u;
        __syncthreads();
    }
    if (t < nb) g_bsum[t] = sh[t] - v;   // exclusive prefix
}

// ---- CSR scan C: per-block local scan + block offset -> g_off, g_cur ----
__global__ void k_scanC(int n) {
    __shared__ int sh[SCAN_B];
    int t = threadIdx.x;
    int i = blockIdx.x * SCAN_B + t;
    int v = (i < n) ? g_deg[i] : 0;
    sh[t] = v;
    __syncthreads();
#pragma unroll
    for (int o = 1; o < SCAN_B; o <<= 1) {
        int u = (t >= o) ? sh[t - o] : 0;
        __syncthreads();
        sh[t] += u;
        __syncthreads();
    }
    int excl = sh[t] - v + g_bsum[blockIdx.x];
    if (i < n) {
        g_off[i] = excl;
        g_cur[i] = excl;
        if (i == n - 1) g_off[n] = excl + v;
    }
}

// ---- CSR build: scatter sources (edges + self loops) ----
__global__ void k_scatter(const int* __restrict__ ei, int e, int n) {
    int idx = blockIdx.x * blockDim.x + threadIdx.x;
    int et = e + n;
    if (idx >= et) return;
    int s, d;
    if (idx < e) { s = ei[idx]; d = ei[e + idx]; } else { s = d = idx - e; }
    int pos = atomicAdd(&g_cur[d], 1);
    g_csrc[pos] = s;
}

// ---- layer1 GEMM [N,27]x[27,64] + attention scores ----
// 256 threads = 64 cols x 4 node-slots; 32 nodes per block (8 groups).
// W1 column cached in registers; a_src/a_dst flatten to a[col].
__global__ void k_gemm1(const float* __restrict__ x, const float* __restrict__ W1,
                        const float* __restrict__ a_src, const float* __restrict__ a_dst,
                        int n) {
    __shared__ float xs[32 * 27];
    int t = threadIdx.x;
    int col = t & 63, slot = t >> 6;     // 4 slots
    float wcol[27];
#pragma unroll
    for (int k = 0; k < 27; k++) wcol[k] = W1[k * 64 + col];
    float asv = a_src[col], adv = a_dst[col];
    int base = blockIdx.x * 32;
    // load 32 nodes x 27 feats
    for (int i = t; i < 32 * 27; i += 256) {
        int nn = base + i / 27;
        xs[i] = (nn < n) ? x[nn * 27 + i % 27] : 0.f;
    }
    __syncthreads();
#pragma unroll
    for (int g = 0; g < 8; g++) {
        int nl = g * 4 + slot;           // local node 0..31
        int node = base + nl;
        const float* xr = &xs[nl * 27];
        float h = 0.f;
#pragma unroll
        for (int k = 0; k < 27; k++) h = fmaf(xr[k], wcol[k], h);
        float vs = h * asv, vd = h * adv;
#pragma unroll
        for (int o = 8; o >= 1; o >>= 1) {
            vs += __shfl_down_sync(0xffffffffu, vs, o, 16);
            vd += __shfl_down_sync(0xffffffffu, vd, o, 16);
        }
        if (node < n) {
            ((float*)g_h1)[node * 64 + col] = h;
            if ((col & 15) == 0) {
                g_ssrc1[node * 4 + (col >> 4)] = vs;
                g_sdst1[node * 4 + (col >> 4)] = vd;
            }
        }
    }
}

// ---- layer1 softmax: one warp per dst node ----
__global__ void k_soft1(int n) {
    int w = (blockIdx.x * blockDim.x + threadIdx.x) >> 5;
    int lane = threadIdx.x & 31;
    if (w >= n) return;
    int off = g_off[w], end = g_off[w + 1];
    float4 sd = *(const float4*)&g_sdst1[w * 4];
    float4 mx = make_float4(-1e30f, -1e30f, -1e30f, -1e30f);
    for (int p = off + lane; p < end; p += 32) {
        int s = g_csrc[p];
        float4 ss = *(const float4*)&g_ssrc1[s * 4];
        float4 a = make_float4(lrelu(ss.x + sd.x), lrelu(ss.y + sd.y),
                               lrelu(ss.z + sd.z), lrelu(ss.w + sd.w));
        g_cw1[p] = a;
        mx.x = fmaxf(mx.x, a.x); mx.y = fmaxf(mx.y, a.y);
        mx.z = fmaxf(mx.z, a.z); mx.w = fmaxf(mx.w, a.w);
    }
#pragma unroll
    for (int o = 16; o >= 1; o >>= 1) {
        mx.x = fmaxf(mx.x, __shfl_xor_sync(0xffffffffu, mx.x, o));
        mx.y = fmaxf(mx.y, __shfl_xor_sync(0xffffffffu, mx.y, o));
        mx.z = fmaxf(mx.z, __shfl_xor_sync(0xffffffffu, mx.z, o));
        mx.w = fmaxf(mx.w, __shfl_xor_sync(0xffffffffu, mx.w, o));
    }
    float4 sum = make_float4(0.f, 0.f, 0.f, 0.f);
    for (int p = off + lane; p < end; p += 32) {
        float4 a = g_cw1[p];
        float4 wv = make_float4(__expf(a.x - mx.x), __expf(a.y - mx.y),
                                __expf(a.z - mx.z), __expf(a.w - mx.w));
        g_cw1[p] = wv;
        sum.x += wv.x; sum.y += wv.y; sum.z += wv.z; sum.w += wv.w;
    }
#pragma unroll
    for (int o = 16; o >= 1; o >>= 1) {
        sum.x += __shfl_xor_sync(0xffffffffu, sum.x, o);
        sum.y += __shfl_xor_sync(0xffffffffu, sum.y, o);
        sum.z += __shfl_xor_sync(0xffffffffu, sum.z, o);
        sum.w += __shfl_xor_sync(0xffffffffu, sum.w, o);
    }
    float4 inv = make_float4(1.f / (sum.x + 1e-16f), 1.f / (sum.y + 1e-16f),
                             1.f / (sum.z + 1e-16f), 1.f / (sum.w + 1e-16f));
    for (int p = off + lane; p < end; p += 32) {
        float4 wv = g_cw1[p];
        wv.x *= inv.x; wv.y *= inv.y; wv.z *= inv.z; wv.w *= inv.w;
        g_cw1[p] = wv;
    }
}

// ---- layer1 gather-aggregate + bias + ELU + fused layer2 scores ----
// 16 threads per node (half-warp groups).
__global__ void k_gagg1(const float* __restrict__ b1, int n) {
    int gid = blockIdx.x * blockDim.x + threadIdx.x;
    int node = gid >> 4;
    if (node >= n) return;
    int q = gid & 15;               // float4 chunk 0..15, head = q>>2
    int head = q >> 2;
    int off = g_off[node], end = g_off[node + 1];
    float4 acc = make_float4(0.f, 0.f, 0.f, 0.f);
    for (int p = off; p < end; p++) {
        int s = g_csrc[p];
        float c = ((const float*)g_cw1)[p * 4 + head];
        float4 h = g_h1[s * 16 + q];
        acc.x = fmaf(c, h.x, acc.x); acc.y = fmaf(c, h.y, acc.y);
        acc.z = fmaf(c, h.z, acc.z); acc.w = fmaf(c, h.w, acc.w);
    }
    float4 b = ((const float4*)b1)[q];
    acc.x = elu(acc.x + b.x); acc.y = elu(acc.y + b.y);
    acc.z = elu(acc.z + b.z); acc.w = elu(acc.w + b.w);
    g_h1o[node * 16 + q] = acc;
    // fused layer2 attention scores: s = h1o . (W2 @ a)
    float4 ps = ((const float4*)g_psrc)[q];
    float4 pd = ((const float4*)g_pdst)[q];
    float vs = acc.x * ps.x + acc.y * ps.y + acc.z * ps.z + acc.w * ps.w;
    float vd = acc.x * pd.x + acc.y * pd.y + acc.z * pd.z + acc.w * pd.w;
#pragma unroll
    for (int o = 8; o >= 1; o >>= 1) {
        vs += __shfl_down_sync(0xffffffffu, vs, o, 16);
        vd += __shfl_down_sync(0xffffffffu, vd, o, 16);
    }
    if (q == 0) { g_ssrc2[node] = vs; g_sdst2[node] = vd; }
}

// ---- layer2 softmax: one warp per dst node ----
__global__ void k_soft2(int n) {
    int w = (blockIdx.x * blockDim.x + threadIdx.x) >> 5;
    int lane = threadIdx.x & 31;
    if (w >= n) return;
    int off = g_off[w], end = g_off[w + 1];
    float sd = g_sdst2[w];
    float mx = -1e30f;
    for (int p = off + lane; p < end; p += 32) {
        float a = lrelu(g_ssrc2[g_csrc[p]] + sd);
        g_cw2[p] = a;
        mx = fmaxf(mx, a);
    }
#pragma unroll
    for (int o = 16; o >= 1; o >>= 1)
        mx = fmaxf(mx, __shfl_xor_sync(0xffffffffu, mx, o));
    float sum = 0.f;
    for (int p = off + lane; p < end; p += 32) {
        float wv = __expf(g_cw2[p] - mx);
        g_cw2[p] = wv;
        sum += wv;
    }
#pragma unroll
    for (int o = 16; o >= 1; o >>= 1)
        sum += __shfl_xor_sync(0xffffffffu, sum, o);
    float inv = 1.f / (sum + 1e-16f);
    for (int p = off + lane; p < end; p += 32)
        g_cw2[p] *= inv;
}

// ---- layer2 aggregate in 64-dim: agg64[d] = sum_e coef_e * h1o[src] ----
__global__ void k_gagg2(int n) {
    int gid = blockIdx.x * blockDim.x + threadIdx.x;
    int node = gid >> 4;
    if (node >= n) return;
    int q = gid & 15;
    int off = g_off[node], end = g_off[node + 1];
    float4 acc = make_float4(0.f, 0.f, 0.f, 0.f);
    for (int p = off; p < end; p++) {
        int s = g_csrc[p];
        float c = g_cw2[p];
        float4 h = g_h1o[s * 16 + q];
        acc.x = fmaf(c, h.x, acc.x); acc.y = fmaf(c, h.y, acc.y);
        acc.z = fmaf(c, h.z, acc.z); acc.w = fmaf(c, h.w, acc.w);
    }
    g_agg64[node * 16 + q] = acc;
}

// ---- layer2 post-GEMM: [N,64]x[64,256] + bias + ELU + graph max-pool ----
__global__ void k_gemm2p(const float* __restrict__ W2, const float* __restrict__ b2,
                         const int* __restrict__ batch, int n) {
    __shared__ float Wsh[32 * 256];
    __shared__ float xs[8][64];
    int t = threadIdx.x;  // 256 threads = 256 cols
    int n0 = blockIdx.x * 8;
    float acc[8] = {0.f, 0.f, 0.f, 0.f, 0.f, 0.f, 0.f, 0.f};
    for (int i = t; i < 8 * 64; i += 256) {
        int nl = i >> 6, k = i & 63;
        int nn = n0 + nl;
        xs[nl][k] = (nn < n) ? ((const float*)g_agg64)[nn * 64 + k] : 0.f;
    }
    for (int kc = 0; kc < 2; kc++) {
        __syncthreads();
        for (int i = t; i < 32 * 256; i += 256) Wsh[i] = W2[kc * 32 * 256 + i];
        __syncthreads();
#pragma unroll
        for (int k = 0; k < 32; k++) {
            float w = Wsh[k * 256 + t];
#pragma unroll
            for (int nl = 0; nl < 8; nl++)
                acc[nl] = fmaf(xs[nl][kc * 32 + k], w, acc[nl]);
        }
    }
    float bb = b2[t];
    for (int nl = 0; nl < 8; nl++) {
        int nn = n0 + nl;
        if (nn < n) {
            float v = elu(acc[nl] + bb);
            atomicMax(&g_pool[batch[nn] * 256 + t], fenc(v));
        }
    }
}

// ---- fused MLP head: per-graph block, 1024 threads ----
// pooled[256] -> relu(256x512) -> relu(512x1024) -> 1024x4 logits
__global__ void k_mlp(const float* __restrict__ Wl1, const float* __restrict__ bl1,
                      const float* __restrict__ Wl2, const float* __restrict__ bl2,
                      const float* __restrict__ Wl3, const float* __restrict__ bl3,
                      float* __restrict__ out) {
    __shared__ float ps[256];
    __shared__ float z1[512];
    __shared__ float z2[1024];
    int g = blockIdx.x, t = threadIdx.x;  // 1024 threads
    if (t < 256) ps[t] = fdec(g_pool[g * 256 + t]);
    __syncthreads();
    if (t < 512) {
        float acc = 0.f;
        for (int k = 0; k < 256; k++) acc = fmaf(ps[k], Wl1[k * 512 + t], acc);
        acc += bl1[t];
        z1[t] = acc > 0.f ? acc : 0.f;
    }
    __syncthreads();
    {
        float acc = 0.f;
        for (int k = 0; k < 512; k++) acc = fmaf(z1[k], Wl2[k * 1024 + t], acc);
        acc += bl2[t];
        z2[t] = acc > 0.f ? acc : 0.f;
    }
    __syncthreads();
    if (t < 128) {
        int wj = t >> 5;       // 4 warps, one per output col
        int lane = t & 31;
        float acc = 0.f;
        for (int k = lane; k < 1024; k += 32)
            acc = fmaf(z2[k], Wl3[k * 4 + wj], acc);
#pragma unroll
        for (int o = 16; o >= 1; o >>= 1) acc += __shfl_down_sync(0xffffffffu, acc, o);
        if (lane == 0) out[g * 4 + wj] = acc + bl3[wj];
    }
}

// ----------------------------------------------------------------------------
extern "C" void kernel_launch(void* const* d_in, const int* in_sizes, int n_in,
                              void* d_out, int out_size) {
    const float* x      = (const float*)d_in[0];
    const int*   ei     = (const int*)d_in[1];
    const int*   batch  = (const int*)d_in[2];
    const float* W1     = (const float*)d_in[3];
    const float* a_src1 = (const float*)d_in[4];
    const float* a_dst1 = (const float*)d_in[5];
    const float* b1     = (const float*)d_in[6];
    const float* W2     = (const float*)d_in[7];
    const float* a_src2 = (const float*)d_in[8];
    const float* a_dst2 = (const float*)d_in[9];
    const float* b2     = (const float*)d_in[10];
    const float* Wl1    = (const float*)d_in[11];
    const float* bl1    = (const float*)d_in[12];
    const float* Wl2    = (const float*)d_in[13];
    const float* bl2    = (const float*)d_in[14];
    const float* Wl3    = (const float*)d_in[15];
    const float* bl3    = (const float*)d_in[16];

    int n = in_sizes[0] / 27;
    int e = in_sizes[1] / 2;
    int et = e + n;
    int nb = (n + SCAN_B - 1) / SCAN_B;

    k_prep<<<256, 256>>>(n);
    k_hist<<<(e + 255) / 256, 256>>>(ei, e);
    k_proj<<<4, 512>>>(W2, a_src2, a_dst2);
    k_gemm1<<<(n + 31) / 32, 256>>>(x, W1, a_src1, a_dst1, n);
    k_scanA<<<nb, SCAN_B>>>(n);
    k_scanB<<<1, NB_MAX>>>(nb);
    k_scanC<<<nb, SCAN_B>>>(n);
    k_scatter<<<(et + 255) / 256, 256>>>(ei, e, n);
    k_soft1<<<(n * 32 + 255) / 256, 256>>>(n);
    k_gagg1<<<(n * 16 + 255) / 256, 256>>>(b1, n);
    k_soft2<<<(n * 32 + 255) / 256, 256>>>(n);
    k_gagg2<<<(n * 16 + 255) / 256, 256>>>(n);
    k_gemm2p<<<(n + 7) / 8, 256>>>(W2, b2, batch, n);
    k_mlp<<<GG, 1024>>>(Wl1, bl1, Wl2, bl2, Wl3, bl3, (float*)d_out);
}